// round 12
// baseline (speedup 1.0000x reference)
#include <cuda_runtime.h>
#include <cstdint>
#include <cfloat>

#define EPS 1e-5f

// B=4, C=64, N=4096, OUT=128, K=20, DIL=2

// ---------------- scratch (device globals; no allocation allowed) ----------------
__device__ __align__(16) float g_rt[4 * 4096 * 128];    // residual, transposed [b][n][o]
__device__ __align__(16) float g_hb[4 * 4096 * 16];     // bottleneck features [b][n][ch]
__device__ __align__(16) float g_sq[4 * 4096];          // squared norms
__device__ int   g_idx[4 * 4096 * 20];                  // final knn indices
__device__ __align__(16) float g_wdt[96 * 128];         // folded + transposed W_dec [j][o]
__device__ __align__(16) float g_kd[4 * 16 * 4096 * 20]; // partial top-20 dists [b][list][n][20]
__device__ int   g_ki[4 * 16 * 4096 * 20];               // partial top-20 idx

// ---------------- f32x2 helpers (Blackwell packed fp32) ----------------
__device__ __forceinline__ unsigned long long fma2(unsigned long long a,
                                                   unsigned long long b,
                                                   unsigned long long c) {
    unsigned long long d;
    asm("fma.rn.f32x2 %0, %1, %2, %3;" : "=l"(d) : "l"(a), "l"(b), "l"(c));
    return d;
}
__device__ __forceinline__ unsigned long long pack2(float f) {
    unsigned long long d;
    unsigned u = __float_as_uint(f);
    asm("mov.b64 %0, {%1, %2};" : "=l"(d) : "r"(u), "r"(u));
    return d;
}
__device__ __forceinline__ void unpack2(unsigned long long a, float& lo, float& hi) {
    unsigned ulo, uhi;
    asm("mov.b64 {%0, %1}, %2;" : "=r"(ulo), "=r"(uhi) : "l"(a));
    lo = __uint_as_float(ulo); hi = __uint_as_float(uhi);
}

// ---------------- cp.async helpers ----------------
__device__ __forceinline__ void cpa16(uint32_t saddr, const void* g) {
    asm volatile("cp.async.cg.shared.global [%0], [%1], 16;" :: "r"(saddr), "l"(g));
}
__device__ __forceinline__ void cpa_commit() {
    asm volatile("cp.async.commit_group;");
}
__device__ __forceinline__ void cpa_wait0() {
    asm volatile("cp.async.wait_group 0;");
}

// =====================================================================
// Kernel 1: prologue — residual conv (BN+ReLU folded), bottleneck conv,
//           squared norms.  128 threads = 128 points, grid (32, B).
// =====================================================================
__global__ void __launch_bounds__(128) k_prologue(
    const float* __restrict__ x,
    const float* __restrict__ Wr, const float* __restrict__ gr, const float* __restrict__ br,
    const float* __restrict__ mr, const float* __restrict__ vr,
    const float* __restrict__ Wb, const float* __restrict__ gb, const float* __restrict__ bbi,
    const float* __restrict__ mb, const float* __restrict__ vb)
{
    __shared__ __align__(16) float Wrs[128 * 64];
    __shared__ __align__(16) float Wbs[16 * 64];
    __shared__ float srs[128], trs[128], sbs[16], tbs[16];

    int t = threadIdx.x;
    int b = blockIdx.y;
    int n = blockIdx.x * 128 + t;

    { float s = gr[t] * rsqrtf(vr[t] + EPS); srs[t] = s; trs[t] = br[t] - mr[t] * s; }
    if (t < 16) { float s = gb[t] * rsqrtf(vb[t] + EPS); sbs[t] = s; tbs[t] = bbi[t] - mb[t] * s; }
    __syncthreads();
    for (int li = t; li < 128 * 64; li += 128) Wrs[li] = Wr[li] * srs[li >> 6];
    for (int li = t; li < 16 * 64; li += 128)  Wbs[li] = Wb[li] * sbs[li >> 6];
    __syncthreads();

    float xq[64];
    const float* xp = x + (size_t)b * 64 * 4096 + n;
#pragma unroll
    for (int c = 0; c < 64; ++c) xq[c] = xp[c * 4096];

    float sq = 0.f;
#pragma unroll
    for (int c = 0; c < 64; ++c) sq = fmaf(xq[c], xq[c], sq);
    g_sq[b * 4096 + n] = sq;

    float* rout = g_rt + (size_t)(b * 4096 + n) * 128;
#pragma unroll 1
    for (int o0 = 0; o0 < 128; o0 += 4) {
        float acc[4];
#pragma unroll
        for (int r = 0; r < 4; ++r) acc[r] = trs[o0 + r];
#pragma unroll
        for (int c4 = 0; c4 < 16; ++c4) {
#pragma unroll
            for (int r = 0; r < 4; ++r) {
                float4 w = *(const float4*)&Wrs[(o0 + r) * 64 + c4 * 4];
                acc[r] = fmaf(w.x, xq[c4 * 4 + 0], acc[r]);
                acc[r] = fmaf(w.y, xq[c4 * 4 + 1], acc[r]);
                acc[r] = fmaf(w.z, xq[c4 * 4 + 2], acc[r]);
                acc[r] = fmaf(w.w, xq[c4 * 4 + 3], acc[r]);
            }
        }
        float4 o;
        o.x = fmaxf(acc[0], 0.f); o.y = fmaxf(acc[1], 0.f);
        o.z = fmaxf(acc[2], 0.f); o.w = fmaxf(acc[3], 0.f);
        *(float4*)&rout[o0] = o;
    }

    float* hout = g_hb + (size_t)(b * 4096 + n) * 16;
#pragma unroll 1
    for (int o0 = 0; o0 < 16; o0 += 4) {
        float acc[4];
#pragma unroll
        for (int r = 0; r < 4; ++r) acc[r] = tbs[o0 + r];
#pragma unroll
        for (int c4 = 0; c4 < 16; ++c4) {
#pragma unroll
            for (int r = 0; r < 4; ++r) {
                float4 w = *(const float4*)&Wbs[(o0 + r) * 64 + c4 * 4];
                acc[r] = fmaf(w.x, xq[c4 * 4 + 0], acc[r]);
                acc[r] = fmaf(w.y, xq[c4 * 4 + 1], acc[r]);
                acc[r] = fmaf(w.z, xq[c4 * 4 + 2], acc[r]);
                acc[r] = fmaf(w.w, xq[c4 * 4 + 3], acc[r]);
            }
        }
        float4 o;
        o.x = fmaxf(acc[0], 0.f); o.y = fmaxf(acc[1], 0.f);
        o.z = fmaxf(acc[2], 0.f); o.w = fmaxf(acc[3], 0.f);
        *(float4*)&hout[o0] = o;
    }
}

// =====================================================================
// Kernel 2: fold W_dec with BN scale and transpose to [j][o]
// =====================================================================
__global__ void k_foldw(const float* __restrict__ Wd, const float* __restrict__ gd,
                        const float* __restrict__ vd)
{
    int li = blockIdx.x * blockDim.x + threadIdx.x;
    if (li < 96 * 128) {
        int j = li >> 7, o = li & 127;
        float s = gd[o] * rsqrtf(vd[o] + EPS);
        g_wdt[li] = Wd[o * 96 + j] * s;
    }
}

// =====================================================================
// Kernel 3a: KNN stage 1.
// grid (32 qtiles, 4 cand-columns, B), 256 threads, 1 block/SM.
// Thread = (qp = t&63 -> queries qp and qp+64 [conflict-free LDS];
// col = t>>6 -> 16 cands of each 64-cand tile).  cp.async double-
// buffered candidate tiles; query tile vectorized [ch4][q][4];
// 2q x 16m FFMA2 register tile.  Emits 16 sorted partial top-20
// lists per query across the grid.
// =====================================================================
// dynamic smem layout (floats):
//   qT2 [16][128][4]            : 8192
//   ms  [2][64][64]             : 8192
//   sqs [2][64]                 : 128
#define KNN1_SMEM_BYTES ((8192 + 8192 + 128) * 4)

__global__ void __launch_bounds__(256, 1) k_knn1(const float* __restrict__ x)
{
    extern __shared__ __align__(16) float dsm[];
    float* qT2 = dsm;                  // 8192
    float* ms  = dsm + 8192;           // 2 * 4096
    float* sqs = dsm + 8192 + 8192;    // 2 * 64

    int t = threadIdx.x;
    int qp = t & 63, col = t >> 6;
    int b = blockIdx.z;
    int qg0 = blockIdx.x * 128;
    int mbase0 = blockIdx.y * 1024;
    const float* xb = x + (size_t)b * 64 * 4096;

    // fill query tile, vectorized layout [ch4][q][4]
    for (int li = t; li < 8192; li += 256) {
        int ch = li >> 7, q = li & 127;
        qT2[((ch >> 2) * 128 + q) * 4 + (ch & 3)] = xb[ch * 4096 + qg0 + q];
    }

    // prefetch candidate tile 0
    uint32_t ms_s  = (uint32_t)__cvta_generic_to_shared(ms);
    uint32_t sqs_s = (uint32_t)__cvta_generic_to_shared(sqs);
    {
#pragma unroll
        for (int i = 0; i < 4; ++i) {
            int f4 = t + 256 * i;
            int row = f4 >> 4, c4 = f4 & 15;
            cpa16(ms_s + f4 * 16, xb + row * 4096 + mbase0 + c4 * 4);
        }
        if (t < 16) cpa16(sqs_s + t * 16, g_sq + b * 4096 + mbase0 + t * 4);
        cpa_commit();
    }

    float td0[20], td1[20]; int ti0[20], ti1[20];
#pragma unroll
    for (int j = 0; j < 20; ++j) {
        td0[j] = FLT_MAX; ti0[j] = 0x7fffffff;
        td1[j] = FLT_MAX; ti1[j] = 0x7fffffff;
    }

#pragma unroll 1
    for (int tile = 0; tile < 16; ++tile) {
        int cur = tile & 1;
        cpa_wait0();
        __syncthreads();

        if (tile + 1 < 16) {
            int nb = (tile + 1) & 1;
            int mb = mbase0 + (tile + 1) * 64;
#pragma unroll
            for (int i = 0; i < 4; ++i) {
                int f4 = t + 256 * i;
                int row = f4 >> 4, c4 = f4 & 15;
                cpa16(ms_s + (nb * 4096 + f4 * 4) * 4, xb + row * 4096 + mb + c4 * 4);
            }
            if (t < 16) cpa16(sqs_s + (nb * 64 + t * 4) * 4, g_sq + b * 4096 + mb + t * 4);
            cpa_commit();
        }

        const float* mcur = ms + cur * 4096;
        unsigned long long a0[8], a1[8];
#pragma unroll
        for (int i = 0; i < 8; ++i) { a0[i] = 0ull; a1[i] = 0ull; }

#pragma unroll 4
        for (int ch4 = 0; ch4 < 16; ++ch4) {
            float4 qa = *(const float4*)&qT2[(ch4 * 128 + qp) * 4];        // query qp
            float4 qb = *(const float4*)&qT2[(ch4 * 128 + qp + 64) * 4];   // query qp+64
            float qav[4] = {qa.x, qa.y, qa.z, qa.w};
            float qbv[4] = {qb.x, qb.y, qb.z, qb.w};
#pragma unroll
            for (int cc = 0; cc < 4; ++cc) {
                unsigned long long qqa = pack2(qav[cc]);
                unsigned long long qqb = pack2(qbv[cc]);
                const ulonglong2* mr =
                    (const ulonglong2*)&mcur[(ch4 * 4 + cc) * 64 + col * 16];
                ulonglong2 v0 = mr[0], v1 = mr[1], v2 = mr[2], v3 = mr[3];
                a0[0] = fma2(qqa, v0.x, a0[0]); a0[1] = fma2(qqa, v0.y, a0[1]);
                a0[2] = fma2(qqa, v1.x, a0[2]); a0[3] = fma2(qqa, v1.y, a0[3]);
                a0[4] = fma2(qqa, v2.x, a0[4]); a0[5] = fma2(qqa, v2.y, a0[5]);
                a0[6] = fma2(qqa, v3.x, a0[6]); a0[7] = fma2(qqa, v3.y, a0[7]);
                a1[0] = fma2(qqb, v0.x, a1[0]); a1[1] = fma2(qqb, v0.y, a1[1]);
                a1[2] = fma2(qqb, v1.x, a1[2]); a1[3] = fma2(qqb, v1.y, a1[3]);
                a1[4] = fma2(qqb, v2.x, a1[4]); a1[5] = fma2(qqb, v2.y, a1[5]);
                a1[6] = fma2(qqb, v3.x, a1[6]); a1[7] = fma2(qqb, v3.y, a1[7]);
            }
        }

        int mtile = mbase0 + tile * 64 + col * 16;
        const float* sqc = sqs + cur * 64 + col * 16;
#pragma unroll
        for (int j = 0; j < 8; ++j) {
            float d0, d1;
            unpack2(a0[j], d0, d1);
            float v0 = fmaf(-2.f, d0, sqc[2 * j]);
            float v1 = fmaf(-2.f, d1, sqc[2 * j + 1]);
            if (v0 < td0[19]) {
                float dv = v0; int mi = mtile + 2 * j;
#pragma unroll
                for (int jj = 0; jj < 20; ++jj)
                    if (dv < td0[jj]) { float td = td0[jj]; td0[jj] = dv; dv = td;
                                        int ti = ti0[jj]; ti0[jj] = mi; mi = ti; }
            }
            if (v1 < td0[19]) {
                float dv = v1; int mi = mtile + 2 * j + 1;
#pragma unroll
                for (int jj = 0; jj < 20; ++jj)
                    if (dv < td0[jj]) { float td = td0[jj]; td0[jj] = dv; dv = td;
                                        int ti = ti0[jj]; ti0[jj] = mi; mi = ti; }
            }
            unpack2(a1[j], d0, d1);
            v0 = fmaf(-2.f, d0, sqc[2 * j]);
            v1 = fmaf(-2.f, d1, sqc[2 * j + 1]);
            if (v0 < td1[19]) {
                float dv = v0; int mi = mtile + 2 * j;
#pragma unroll
                for (int jj = 0; jj < 20; ++jj)
                    if (dv < td1[jj]) { float td = td1[jj]; td1[jj] = dv; dv = td;
                                        int ti = ti1[jj]; ti1[jj] = mi; mi = ti; }
            }
            if (v1 < td1[19]) {
                float dv = v1; int mi = mtile + 2 * j + 1;
#pragma unroll
                for (int jj = 0; jj < 20; ++jj)
                    if (dv < td1[jj]) { float td = td1[jj]; td1[jj] = dv; dv = td;
                                        int ti = ti1[jj]; ti1[jj] = mi; mi = ti; }
            }
        }
    }

    int list = blockIdx.y * 4 + col;
    size_t ba = (((size_t)b * 16 + list) * 4096 + qg0 + qp) * 20;
#pragma unroll
    for (int j = 0; j < 20; ++j) { g_kd[ba + j] = td0[j]; g_ki[ba + j] = ti0[j]; }
    ba += (size_t)64 * 20;   // query qp + 64
#pragma unroll
    for (int j = 0; j < 20; ++j) { g_kd[ba + j] = td1[j]; g_ki[ba + j] = ti1[j]; }
}

// =====================================================================
// Kernel 3b: KNN stage 2 — warp-parallel stable 16-way merge.
// Each 16-lane half-warp merges one query's 16 sorted lists; lane = list.
// grid 1024 x 256 => 16384 half-warps = all queries.
// =====================================================================
__global__ void __launch_bounds__(256) k_knn2()
{
    int t = threadIdx.x;
    int gw = (blockIdx.x * 256 + t) >> 5;       // global warp id [0, 8192)
    int half = (t >> 4) & 1;
    int sl = t & 15;                             // lane within half = list id
    int qid = gw * 2 + half;                     // [0, 16384)
    int b = qid >> 12, q = qid & 4095;

    size_t base = (((size_t)b * 16 + sl) * 4096 + q) * 20;
    const float* dp = g_kd + base;
    const int*   ip = g_ki + base;
    int pos = 0;
    float hd = dp[0];
    int   hi = ip[0];
    int* op = g_idx + (size_t)qid * 20;

#pragma unroll 1
    for (int k = 0; k < 20; ++k) {
        float md = hd; int mi = hi;
#pragma unroll
        for (int off = 8; off >= 1; off >>= 1) {
            float od = __shfl_xor_sync(0xffffffffu, md, off, 16);
            int   oi = __shfl_xor_sync(0xffffffffu, mi, off, 16);
            if (od < md || (od == md && oi < mi)) { md = od; mi = oi; }
        }
        if (sl == 0) op[k] = mi;
        if (mi == hi) {      // winner lane advances (indices unique across lists)
            ++pos;
            if (pos < 20) { hd = dp[pos]; hi = ip[pos]; }
            else          { hd = FLT_MAX; hi = 0x7fffffff; }
        }
    }
}

// =====================================================================
// Kernel 4: epilogue.  one warp per point (8 points / 256-thr block).
// gather -> gcn1 (K=20) + gcn2 (even k) + global max -> decoder (W_dec
// staged through smem in 16-row chunks) + residual.
// =====================================================================
__global__ void __launch_bounds__(256) k_epilogue(
    const float* __restrict__ Wg1, const float* __restrict__ g1g, const float* __restrict__ g1b,
    const float* __restrict__ g1m, const float* __restrict__ g1v,
    const float* __restrict__ Wg2, const float* __restrict__ g2g, const float* __restrict__ g2b,
    const float* __restrict__ g2m, const float* __restrict__ g2v,
    const float* __restrict__ gdg, const float* __restrict__ gdb,
    const float* __restrict__ gdm, const float* __restrict__ gdv,
    float* __restrict__ out)
{
    __shared__ __align__(16) float W1s[32 * 32];   // [in][out], BN-folded
    __shared__ __align__(16) float W2s[32 * 32];
    __shared__ float t1s[32], t2s[32], s1s[32], s2s[32];
    __shared__ __align__(16) float tds[128];
    __shared__ __align__(16) float fns[8][20][16];
    __shared__ __align__(16) float ctrs[8][16];
    __shared__ float afs[8][96];
    __shared__ __align__(16) float wsm[16][128];   // W_dec chunk stage

    int t = threadIdx.x;
    if (t < 32)      { float s = g1g[t] * rsqrtf(g1v[t] + EPS); s1s[t] = s; t1s[t] = g1b[t] - g1m[t] * s; }
    else if (t < 64) { int i = t - 32; float s = g2g[i] * rsqrtf(g2v[i] + EPS); s2s[i] = s; t2s[i] = g2b[i] - g2m[i] * s; }
    if (t < 128)     { float s = gdg[t] * rsqrtf(gdv[t] + EPS); tds[t] = gdb[t] - gdm[t] * s; }
    __syncthreads();
    for (int li = t; li < 1024; li += 256) {
        int i = li >> 5, o = li & 31;
        W1s[li] = Wg1[o * 32 + i] * s1s[o];
        W2s[li] = Wg2[o * 32 + i] * s2s[o];
    }
    __syncthreads();

    int wid = t >> 5, lane = t & 31;
    int g = blockIdx.x * 8 + wid;
    int b = g >> 12, n = g & 4095;

    float* fw = &fns[wid][0][0];
    float* cw = &ctrs[wid][0];
    float* aw = &afs[wid][0];

    if (lane < 20) {
        int nid = g_idx[(size_t)g * 20 + lane];
        const float4* src = (const float4*)(g_hb + (size_t)(b * 4096 + nid) * 16);
        float4* dst = (float4*)(fw + lane * 16);
        dst[0] = src[0]; dst[1] = src[1]; dst[2] = src[2]; dst[3] = src[3];
    } else if (lane < 24) {
        int j = lane - 20;
        ((float4*)cw)[j] = ((const float4*)(g_hb + (size_t)g * 16))[j];
    }
    __syncwarp();

    float w1[32], w2[32];
#pragma unroll
    for (int i = 0; i < 32; ++i) { w1[i] = W1s[i * 32 + lane]; w2[i] = W2s[i * 32 + lane]; }

    // center contribution (channels 16..31 of the graph feature) hoisted
    float base1 = t1s[lane], base2 = t2s[lane];
#pragma unroll
    for (int j = 0; j < 16; ++j) {
        float cv = cw[j];
        base1 = fmaf(w1[16 + j], cv, base1);
        base2 = fmaf(w2[16 + j], cv, base2);
    }

    float o1 = -FLT_MAX, o2v = -FLT_MAX;
#pragma unroll
    for (int k = 0; k < 20; ++k) {
        const float4* fr = (const float4*)(fw + k * 16);
        float fv[16];
#pragma unroll
        for (int j4 = 0; j4 < 4; ++j4) {
            float4 fq = fr[j4];
            fv[j4 * 4 + 0] = fq.x; fv[j4 * 4 + 1] = fq.y;
            fv[j4 * 4 + 2] = fq.z; fv[j4 * 4 + 3] = fq.w;
        }
        float a = base1;
#pragma unroll
        for (int j = 0; j < 16; ++j) a = fmaf(w1[j], fv[j], a);
        a = a > 0.f ? a : 0.2f * a;        // leaky relu
        o1 = fmaxf(o1, a);
        if ((k & 1) == 0) {                // dilated branch: k = 0,2,...,18
            float a2 = base2;
#pragma unroll
            for (int j = 0; j < 16; ++j) a2 = fmaf(w2[j], fv[j], a2);
            a2 = a2 > 0.f ? a2 : 0.2f * a2;
            o2v = fmaxf(o2v, a2);
        }
    }

    // global max over f1: ch 0..15 = max over neighbors, ch 16..31 = center
    float gm;
    if (lane < 16) {
        gm = fw[lane];
#pragma unroll
        for (int k = 1; k < 20; ++k) gm = fmaxf(gm, fw[k * 16 + lane]);
    } else {
        gm = cw[lane - 16];
    }
    aw[lane] = o1; aw[32 + lane] = o2v; aw[64 + lane] = gm;
    __syncwarp();

    // decoder: lane handles outputs o = 4*lane .. 4*lane+3; W_dec staged
    // through smem in 16-row chunks shared by all 8 warps
    float4 acc = *(const float4*)&tds[lane * 4];
#pragma unroll 1
    for (int j0 = 0; j0 < 96; j0 += 16) {
        __syncthreads();
        for (int li = t; li < 16 * 128; li += 256)
            wsm[li >> 7][li & 127] = g_wdt[(j0 << 7) + li];
        __syncthreads();
#pragma unroll
        for (int jj = 0; jj < 16; ++jj) {
            float a = aw[j0 + jj];
            float4 w = *(const float4*)&wsm[jj][lane * 4];
            acc.x = fmaf(w.x, a, acc.x); acc.y = fmaf(w.y, a, acc.y);
            acc.z = fmaf(w.z, a, acc.z); acc.w = fmaf(w.w, a, acc.w);
        }
    }
    const float4 rv = *(const float4*)(g_rt + (size_t)g * 128 + lane * 4);
    float r0 = fmaxf(acc.x, 0.f) + rv.x;
    float r1 = fmaxf(acc.y, 0.f) + rv.y;
    float r2 = fmaxf(acc.z, 0.f) + rv.z;
    float r3 = fmaxf(acc.w, 0.f) + rv.w;

    size_t ob = ((size_t)b * 128 + lane * 4) * 4096 + n;   // out[b][o][n][0]
    out[ob]            = r0;
    out[ob + 4096]     = r1;
    out[ob + 2 * 4096] = r2;
    out[ob + 3 * 4096] = r3;
}

// =====================================================================
extern "C" void kernel_launch(void* const* d_in, const int* in_sizes, int n_in,
                              void* d_out, int out_size)
{
    (void)in_sizes; (void)n_in; (void)out_size;
    const float* x    = (const float*)d_in[0];
    const float* Wr   = (const float*)d_in[1];
    const float* gr   = (const float*)d_in[2];
    const float* br   = (const float*)d_in[3];
    const float* mr   = (const float*)d_in[4];
    const float* vr   = (const float*)d_in[5];
    const float* Wb   = (const float*)d_in[6];
    const float* gb   = (const float*)d_in[7];
    const float* bbi  = (const float*)d_in[8];
    const float* mb   = (const float*)d_in[9];
    const float* vb   = (const float*)d_in[10];
    const float* Wg1  = (const float*)d_in[11];
    const float* g1g  = (const float*)d_in[12];
    const float* g1b  = (const float*)d_in[13];
    const float* g1m  = (const float*)d_in[14];
    const float* g1v  = (const float*)d_in[15];
    const float* Wg2  = (const float*)d_in[16];
    const float* g2g  = (const float*)d_in[17];
    const float* g2b  = (const float*)d_in[18];
    const float* g2m  = (const float*)d_in[19];
    const float* g2v  = (const float*)d_in[20];
    const float* Wd   = (const float*)d_in[21];
    const float* gdg  = (const float*)d_in[22];
    const float* gdb  = (const float*)d_in[23];
    const float* gdm  = (const float*)d_in[24];
    const float* gdv  = (const float*)d_in[25];
    float* out = (float*)d_out;

    cudaFuncSetAttribute(k_knn1, cudaFuncAttributeMaxDynamicSharedMemorySize,
                         KNN1_SMEM_BYTES);

    k_prologue<<<dim3(32, 4), 128>>>(x, Wr, gr, br, mr, vr, Wb, gb, bbi, mb, vb);
    k_foldw<<<48, 256>>>(Wd, gdg, gdv);
    k_knn1<<<dim3(32, 4, 4), 256, KNN1_SMEM_BYTES>>>(x);
    k_knn2<<<1024, 256>>>();
    k_epilogue<<<2048, 256>>>(Wg1, g1g, g1b, g1m, g1v,
                              Wg2, g2g, g2b, g2m, g2v,
                              gdg, gdb, gdm, gdv, out);
}

// round 13
// speedup vs baseline: 1.7127x; 1.7127x over previous
#include <cuda_runtime.h>
#include <cstdint>
#include <cfloat>

#define EPS 1e-5f

// B=4, C=64, N=4096, OUT=128, K=20, DIL=2

// ---------------- scratch (device globals; no allocation allowed) ----------------
__device__ __align__(16) float g_rt[4 * 4096 * 128];    // residual, transposed [b][n][o]
__device__ __align__(16) float g_hb[4 * 4096 * 16];     // bottleneck features [b][n][ch]
__device__ __align__(16) float g_sq[4 * 4096];          // squared norms
__device__ int   g_idx[4 * 4096 * 20];                  // final knn indices
__device__ __align__(16) float g_wdt[96 * 128];         // folded + transposed W_dec [j][o]
__device__ __align__(16) float g_d2[(size_t)4 * 4096 * 4096];  // rank keys [b*4096+q][m]

// ---------------- f32x2 helpers (Blackwell packed fp32) ----------------
__device__ __forceinline__ unsigned long long fma2(unsigned long long a,
                                                   unsigned long long b,
                                                   unsigned long long c) {
    unsigned long long d;
    asm("fma.rn.f32x2 %0, %1, %2, %3;" : "=l"(d) : "l"(a), "l"(b), "l"(c));
    return d;
}
__device__ __forceinline__ unsigned long long pack2(float f) {
    unsigned long long d;
    unsigned u = __float_as_uint(f);
    asm("mov.b64 %0, {%1, %2};" : "=l"(d) : "r"(u), "r"(u));
    return d;
}
__device__ __forceinline__ void unpack2(unsigned long long a, float& lo, float& hi) {
    unsigned ulo, uhi;
    asm("mov.b64 {%0, %1}, %2;" : "=r"(ulo), "=r"(uhi) : "l"(a));
    lo = __uint_as_float(ulo); hi = __uint_as_float(uhi);
}

// =====================================================================
// Kernel 1: prologue — residual conv (BN+ReLU folded), bottleneck conv,
//           squared norms.  128 threads = 128 points, grid (32, B).
// =====================================================================
__global__ void __launch_bounds__(128) k_prologue(
    const float* __restrict__ x,
    const float* __restrict__ Wr, const float* __restrict__ gr, const float* __restrict__ br,
    const float* __restrict__ mr, const float* __restrict__ vr,
    const float* __restrict__ Wb, const float* __restrict__ gb, const float* __restrict__ bbi,
    const float* __restrict__ mb, const float* __restrict__ vb)
{
    __shared__ __align__(16) float Wrs[128 * 64];
    __shared__ __align__(16) float Wbs[16 * 64];
    __shared__ float srs[128], trs[128], sbs[16], tbs[16];

    int t = threadIdx.x;
    int b = blockIdx.y;
    int n = blockIdx.x * 128 + t;

    { float s = gr[t] * rsqrtf(vr[t] + EPS); srs[t] = s; trs[t] = br[t] - mr[t] * s; }
    if (t < 16) { float s = gb[t] * rsqrtf(vb[t] + EPS); sbs[t] = s; tbs[t] = bbi[t] - mb[t] * s; }
    __syncthreads();
    for (int li = t; li < 128 * 64; li += 128) Wrs[li] = Wr[li] * srs[li >> 6];
    for (int li = t; li < 16 * 64; li += 128)  Wbs[li] = Wb[li] * sbs[li >> 6];
    __syncthreads();

    float xq[64];
    const float* xp = x + (size_t)b * 64 * 4096 + n;
#pragma unroll
    for (int c = 0; c < 64; ++c) xq[c] = xp[c * 4096];

    float sq = 0.f;
#pragma unroll
    for (int c = 0; c < 64; ++c) sq = fmaf(xq[c], xq[c], sq);
    g_sq[b * 4096 + n] = sq;

    float* rout = g_rt + (size_t)(b * 4096 + n) * 128;
#pragma unroll 1
    for (int o0 = 0; o0 < 128; o0 += 4) {
        float acc[4];
#pragma unroll
        for (int r = 0; r < 4; ++r) acc[r] = trs[o0 + r];
#pragma unroll
        for (int c4 = 0; c4 < 16; ++c4) {
#pragma unroll
            for (int r = 0; r < 4; ++r) {
                float4 w = *(const float4*)&Wrs[(o0 + r) * 64 + c4 * 4];
                acc[r] = fmaf(w.x, xq[c4 * 4 + 0], acc[r]);
                acc[r] = fmaf(w.y, xq[c4 * 4 + 1], acc[r]);
                acc[r] = fmaf(w.z, xq[c4 * 4 + 2], acc[r]);
                acc[r] = fmaf(w.w, xq[c4 * 4 + 3], acc[r]);
            }
        }
        float4 o;
        o.x = fmaxf(acc[0], 0.f); o.y = fmaxf(acc[1], 0.f);
        o.z = fmaxf(acc[2], 0.f); o.w = fmaxf(acc[3], 0.f);
        *(float4*)&rout[o0] = o;
    }

    float* hout = g_hb + (size_t)(b * 4096 + n) * 16;
#pragma unroll 1
    for (int o0 = 0; o0 < 16; o0 += 4) {
        float acc[4];
#pragma unroll
        for (int r = 0; r < 4; ++r) acc[r] = tbs[o0 + r];
#pragma unroll
        for (int c4 = 0; c4 < 16; ++c4) {
#pragma unroll
            for (int r = 0; r < 4; ++r) {
                float4 w = *(const float4*)&Wbs[(o0 + r) * 64 + c4 * 4];
                acc[r] = fmaf(w.x, xq[c4 * 4 + 0], acc[r]);
                acc[r] = fmaf(w.y, xq[c4 * 4 + 1], acc[r]);
                acc[r] = fmaf(w.z, xq[c4 * 4 + 2], acc[r]);
                acc[r] = fmaf(w.w, xq[c4 * 4 + 3], acc[r]);
            }
        }
        float4 o;
        o.x = fmaxf(acc[0], 0.f); o.y = fmaxf(acc[1], 0.f);
        o.z = fmaxf(acc[2], 0.f); o.w = fmaxf(acc[3], 0.f);
        *(float4*)&hout[o0] = o;
    }
}

// =====================================================================
// Kernel 2: fold W_dec with BN scale and transpose to [j][o]
// =====================================================================
__global__ void k_foldw(const float* __restrict__ Wd, const float* __restrict__ gd,
                        const float* __restrict__ vd)
{
    int li = blockIdx.x * blockDim.x + threadIdx.x;
    if (li < 96 * 128) {
        int j = li >> 7, o = li & 127;
        float s = gd[o] * rsqrtf(vd[o] + EPS);
        g_wdt[li] = Wd[o * 96 + j] * s;
    }
}

// =====================================================================
// Kernel 3a: k_dist — pure rank-key GEMM.
// grid (32 m-tiles, 32 q-tiles, B), 256 threads.  Tile 128q x 128m,
// full K=64 resident in smem.  Thread computes 8q x 8m via FFMA2.
// Stores key[q][m] = sq[m] - 2*dot(q,m) to g_d2 (row-major per query).
// =====================================================================
// dynamic smem: qs[64][128] + ms[64][128] + sqm[128]
#define DIST_SMEM_BYTES ((64 * 128 * 2 + 128) * 4)

__global__ void __launch_bounds__(256, 2) k_dist(const float* __restrict__ x)
{
    extern __shared__ __align__(16) float dsm[];
    float* qs  = dsm;                  // [k][q]  64*128
    float* ms  = dsm + 64 * 128;       // [k][m]  64*128
    float* sqm = dsm + 2 * 64 * 128;   // [128]

    int t = threadIdx.x;
    int b = blockIdx.z;
    int m0 = blockIdx.x * 128;
    int q0 = blockIdx.y * 128;
    const float* xb = x + (size_t)b * 64 * 4096;

    for (int i = t; i < 2048; i += 256) {
        int k = i >> 5, c4 = i & 31;
        *(float4*)&qs[k * 128 + c4 * 4] = *(const float4*)&xb[k * 4096 + q0 + c4 * 4];
    }
    for (int i = t; i < 2048; i += 256) {
        int k = i >> 5, c4 = i & 31;
        *(float4*)&ms[k * 128 + c4 * 4] = *(const float4*)&xb[k * 4096 + m0 + c4 * 4];
    }
    if (t < 32)
        *(float4*)&sqm[t * 4] = *(const float4*)&g_sq[b * 4096 + m0 + t * 4];
    __syncthreads();

    int tx = t & 15, ty = t >> 4;   // tx -> m group, ty -> q group

    unsigned long long acc[8][4];
#pragma unroll
    for (int qi = 0; qi < 8; ++qi)
#pragma unroll
        for (int mj = 0; mj < 4; ++mj) acc[qi][mj] = 0ull;

#pragma unroll 4
    for (int k = 0; k < 64; ++k) {
        float4 qv0 = *(const float4*)&qs[k * 128 + ty * 8];
        float4 qv1 = *(const float4*)&qs[k * 128 + ty * 8 + 4];
        const ulonglong2* mrp = (const ulonglong2*)&ms[k * 128 + tx * 8];
        ulonglong2 mA = mrp[0], mB = mrp[1];
        float qv[8] = {qv0.x, qv0.y, qv0.z, qv0.w, qv1.x, qv1.y, qv1.z, qv1.w};
#pragma unroll
        for (int qi = 0; qi < 8; ++qi) {
            unsigned long long qq = pack2(qv[qi]);
            acc[qi][0] = fma2(qq, mA.x, acc[qi][0]);
            acc[qi][1] = fma2(qq, mA.y, acc[qi][1]);
            acc[qi][2] = fma2(qq, mB.x, acc[qi][2]);
            acc[qi][3] = fma2(qq, mB.y, acc[qi][3]);
        }
    }

    float sq8[8];
#pragma unroll
    for (int j = 0; j < 8; ++j) sq8[j] = sqm[tx * 8 + j];

#pragma unroll
    for (int qi = 0; qi < 8; ++qi) {
        int qrow = q0 + ty * 8 + qi;
        size_t ro = (((size_t)(b * 4096 + qrow)) << 12) + m0 + tx * 8;
        float d[8];
        unpack2(acc[qi][0], d[0], d[1]);
        unpack2(acc[qi][1], d[2], d[3]);
        unpack2(acc[qi][2], d[4], d[5]);
        unpack2(acc[qi][3], d[6], d[7]);
        float4 o0, o1;
        o0.x = fmaf(-2.f, d[0], sq8[0]); o0.y = fmaf(-2.f, d[1], sq8[1]);
        o0.z = fmaf(-2.f, d[2], sq8[2]); o0.w = fmaf(-2.f, d[3], sq8[3]);
        o1.x = fmaf(-2.f, d[4], sq8[4]); o1.y = fmaf(-2.f, d[5], sq8[5]);
        o1.z = fmaf(-2.f, d[6], sq8[6]); o1.w = fmaf(-2.f, d[7], sq8[7]);
        *(float4*)&g_d2[ro]     = o0;
        *(float4*)&g_d2[ro + 4] = o1;
    }
}

// =====================================================================
// Kernel 3b: k_sel — radix top-20 per query, block per query (128 thr).
// Row of 4096 keys loaded ONCE into registers as order-preserving uints.
// 256-bin histogram on 8 bits/level (refine only if threshold bin too
// fat), compact (key,idx) into 64-bit packed values, then 20 exact
// min-extracts by warp 0 => identical (value, index) order to top_k.
// =====================================================================
#define SEL_CAP 1024

__global__ void __launch_bounds__(128) k_sel()
{
    __shared__ int sh_hist[256];
    __shared__ unsigned long long sh_buf[SEL_CAP];
    __shared__ int sh_T, sh_c0n, sh_cntT, sh_bufn;

    int t = threadIdx.x;
    int qid = blockIdx.y * 4096 + blockIdx.x;     // b*4096 + q
    const float* row = g_d2 + ((size_t)qid << 12);

    // load 32 values -> ordered uints
    unsigned u[32];
#pragma unroll
    for (int i = 0; i < 8; ++i) {
        float4 v = *(const float4*)&row[(i * 128 + t) * 4];
        float f[4] = {v.x, v.y, v.z, v.w};
#pragma unroll
        for (int j = 0; j < 4; ++j) {
            unsigned fu = __float_as_uint(f[j]);
            u[i * 4 + j] = (fu & 0x80000000u) ? ~fu : (fu | 0x80000000u);
        }
    }

    unsigned prefix = 0;
    int c0 = 0;
    int shift = 24;
    unsigned thr = 0;

#pragma unroll 1
    for (;; shift -= 8) {
        // zero histogram
        sh_hist[t] = 0; sh_hist[t + 128] = 0;
        __syncthreads();
        // histogram values matching prefix above (shift+8)
        if (shift == 24) {
#pragma unroll
            for (int i = 0; i < 32; ++i)
                atomicAdd(&sh_hist[u[i] >> 24], 1);
        } else {
            unsigned pref_hi = prefix >> (shift + 8);
#pragma unroll
            for (int i = 0; i < 32; ++i)
                if ((u[i] >> (shift + 8)) == pref_hi)
                    atomicAdd(&sh_hist[(u[i] >> shift) & 0xFF], 1);
        }
        __syncthreads();

        // warp 0: find threshold bin
        if (t < 32) {
            int base = t * 8;
            int loc[8], s = 0;
#pragma unroll
            for (int j = 0; j < 8; ++j) { loc[j] = sh_hist[base + j]; s += loc[j]; }
            int inc = s;
#pragma unroll
            for (int off = 1; off < 32; off <<= 1) {
                int nv = __shfl_up_sync(0xffffffffu, inc, off);
                if (t >= off) inc += nv;
            }
            int cum = inc - s;           // exclusive prefix
            int T = 256, cumB = 0;
#pragma unroll
            for (int j = 0; j < 8; ++j) {
                int nc = cum + loc[j];
                if (T == 256 && c0 + nc >= 20) { T = base + j; cumB = cum; }
                cum = nc;
            }
            unsigned bal = __ballot_sync(0xffffffffu, T < 256);
            int w = __ffs(bal) - 1;
            int Tw   = __shfl_sync(0xffffffffu, T, w);
            int cumBw = __shfl_sync(0xffffffffu, cumB, w);
            if (t == 0) {
                sh_T = Tw;
                sh_c0n = c0 + cumBw;
                sh_cntT = sh_hist[Tw];
            }
        }
        __syncthreads();

        int T = sh_T, c0n = sh_c0n, cntT = sh_cntT;
        thr = prefix | ((unsigned)T << shift);
        if (shift == 0 || c0n + cntT <= SEL_CAP) { c0 = c0n; break; }
        prefix = thr;
        c0 = c0n;
        __syncthreads();   // protect sh_hist reuse next level
    }

    // compact: take values with (u >> shift) <= (thr >> shift)
    if (t == 0) sh_bufn = 0;
    __syncthreads();
    unsigned thr_hi = thr >> shift;
#pragma unroll
    for (int i = 0; i < 32; ++i) {
        if ((u[i] >> shift) <= thr_hi) {
            int pos = atomicAdd(&sh_bufn, 1);
            if (pos < SEL_CAP) {
                int m = 4 * ((i >> 2) * 128 + t) + (i & 3);
                sh_buf[pos] = ((unsigned long long)u[i] << 32) | (unsigned)m;
            }
        }
    }
    __syncthreads();

    // warp 0: 20 exact min-extracts by (key, idx)
    if (t < 32) {
        int cnt = sh_bufn < SEL_CAP ? sh_bufn : SEL_CAP;
        int* op = g_idx + (size_t)qid * 20;
#pragma unroll 1
        for (int k = 0; k < 20; ++k) {
            unsigned long long best = 0xFFFFFFFFFFFFFFFFull;
            int bp = -1;
            for (int i = t; i < cnt; i += 32) {
                unsigned long long v = sh_buf[i];
                if (v < best) { best = v; bp = i; }
            }
#pragma unroll
            for (int off = 16; off >= 1; off >>= 1) {
                unsigned long long ob = __shfl_xor_sync(0xffffffffu, best, off);
                int opp = __shfl_xor_sync(0xffffffffu, bp, off);
                if (ob < best) { best = ob; bp = opp; }
            }
            if (t == 0) {
                op[k] = (int)(best & 0xFFFFFFFFull);
                sh_buf[bp] = 0xFFFFFFFFFFFFFFFFull;
            }
            __syncwarp();
        }
    }
}

// =====================================================================
// Kernel 4: epilogue.  one warp per point (8 points / 256-thr block).
// gather -> gcn1 (K=20) + gcn2 (even k) + global max -> decoder (W_dec
// staged through smem in 16-row chunks) + residual.
// =====================================================================
__global__ void __launch_bounds__(256) k_epilogue(
    const float* __restrict__ Wg1, const float* __restrict__ g1g, const float* __restrict__ g1b,
    const float* __restrict__ g1m, const float* __restrict__ g1v,
    const float* __restrict__ Wg2, const float* __restrict__ g2g, const float* __restrict__ g2b,
    const float* __restrict__ g2m, const float* __restrict__ g2v,
    const float* __restrict__ gdg, const float* __restrict__ gdb,
    const float* __restrict__ gdm, const float* __restrict__ gdv,
    float* __restrict__ out)
{
    __shared__ __align__(16) float W1s[32 * 32];   // [in][out], BN-folded
    __shared__ __align__(16) float W2s[32 * 32];
    __shared__ float t1s[32], t2s[32], s1s[32], s2s[32];
    __shared__ __align__(16) float tds[128];
    __shared__ __align__(16) float fns[8][20][16];
    __shared__ __align__(16) float ctrs[8][16];
    __shared__ float afs[8][96];
    __shared__ __align__(16) float wsm[16][128];   // W_dec chunk stage

    int t = threadIdx.x;
    if (t < 32)      { float s = g1g[t] * rsqrtf(g1v[t] + EPS); s1s[t] = s; t1s[t] = g1b[t] - g1m[t] * s; }
    else if (t < 64) { int i = t - 32; float s = g2g[i] * rsqrtf(g2v[i] + EPS); s2s[i] = s; t2s[i] = g2b[i] - g2m[i] * s; }
    if (t < 128)     { float s = gdg[t] * rsqrtf(gdv[t] + EPS); tds[t] = gdb[t] - gdm[t] * s; }
    __syncthreads();
    for (int li = t; li < 1024; li += 256) {
        int i = li >> 5, o = li & 31;
        W1s[li] = Wg1[o * 32 + i] * s1s[o];
        W2s[li] = Wg2[o * 32 + i] * s2s[o];
    }
    __syncthreads();

    int wid = t >> 5, lane = t & 31;
    int g = blockIdx.x * 8 + wid;
    int b = g >> 12, n = g & 4095;

    float* fw = &fns[wid][0][0];
    float* cw = &ctrs[wid][0];
    float* aw = &afs[wid][0];

    if (lane < 20) {
        int nid = g_idx[(size_t)g * 20 + lane];
        const float4* src = (const float4*)(g_hb + (size_t)(b * 4096 + nid) * 16);
        float4* dst = (float4*)(fw + lane * 16);
        dst[0] = src[0]; dst[1] = src[1]; dst[2] = src[2]; dst[3] = src[3];
    } else if (lane < 24) {
        int j = lane - 20;
        ((float4*)cw)[j] = ((const float4*)(g_hb + (size_t)g * 16))[j];
    }
    __syncwarp();

    float w1[32], w2[32];
#pragma unroll
    for (int i = 0; i < 32; ++i) { w1[i] = W1s[i * 32 + lane]; w2[i] = W2s[i * 32 + lane]; }

    // center contribution (channels 16..31 of the graph feature) hoisted
    float base1 = t1s[lane], base2 = t2s[lane];
#pragma unroll
    for (int j = 0; j < 16; ++j) {
        float cv = cw[j];
        base1 = fmaf(w1[16 + j], cv, base1);
        base2 = fmaf(w2[16 + j], cv, base2);
    }

    float o1 = -FLT_MAX, o2v = -FLT_MAX;
#pragma unroll
    for (int k = 0; k < 20; ++k) {
        const float4* fr = (const float4*)(fw + k * 16);
        float fv[16];
#pragma unroll
        for (int j4 = 0; j4 < 4; ++j4) {
            float4 fq = fr[j4];
            fv[j4 * 4 + 0] = fq.x; fv[j4 * 4 + 1] = fq.y;
            fv[j4 * 4 + 2] = fq.z; fv[j4 * 4 + 3] = fq.w;
        }
        float a = base1;
#pragma unroll
        for (int j = 0; j < 16; ++j) a = fmaf(w1[j], fv[j], a);
        a = a > 0.f ? a : 0.2f * a;        // leaky relu
        o1 = fmaxf(o1, a);
        if ((k & 1) == 0) {                // dilated branch: k = 0,2,...,18
            float a2 = base2;
#pragma unroll
            for (int j = 0; j < 16; ++j) a2 = fmaf(w2[j], fv[j], a2);
            a2 = a2 > 0.f ? a2 : 0.2f * a2;
            o2v = fmaxf(o2v, a2);
        }
    }

    // global max over f1: ch 0..15 = max over neighbors, ch 16..31 = center
    float gm;
    if (lane < 16) {
        gm = fw[lane];
#pragma unroll
        for (int k = 1; k < 20; ++k) gm = fmaxf(gm, fw[k * 16 + lane]);
    } else {
        gm = cw[lane - 16];
    }
    aw[lane] = o1; aw[32 + lane] = o2v; aw[64 + lane] = gm;
    __syncwarp();

    // decoder: lane handles outputs o = 4*lane .. 4*lane+3; W_dec staged
    // through smem in 16-row chunks shared by all 8 warps
    float4 acc = *(const float4*)&tds[lane * 4];
#pragma unroll 1
    for (int j0 = 0; j0 < 96; j0 += 16) {
        __syncthreads();
        for (int li = t; li < 16 * 128; li += 256)
            wsm[li >> 7][li & 127] = g_wdt[(j0 << 7) + li];
        __syncthreads();
#pragma unroll
        for (int jj = 0; jj < 16; ++jj) {
            float a = aw[j0 + jj];
            float4 w = *(const float4*)&wsm[jj][lane * 4];
            acc.x = fmaf(w.x, a, acc.x); acc.y = fmaf(w.y, a, acc.y);
            acc.z = fmaf(w.z, a, acc.z); acc.w = fmaf(w.w, a, acc.w);
        }
    }
    const float4 rv = *(const float4*)(g_rt + (size_t)g * 128 + lane * 4);
    float r0 = fmaxf(acc.x, 0.f) + rv.x;
    float r1 = fmaxf(acc.y, 0.f) + rv.y;
    float r2 = fmaxf(acc.z, 0.f) + rv.z;
    float r3 = fmaxf(acc.w, 0.f) + rv.w;

    size_t ob = ((size_t)b * 128 + lane * 4) * 4096 + n;   // out[b][o][n][0]
    out[ob]            = r0;
    out[ob + 4096]     = r1;
    out[ob + 2 * 4096] = r2;
    out[ob + 3 * 4096] = r3;
}

// =====================================================================
extern "C" void kernel_launch(void* const* d_in, const int* in_sizes, int n_in,
                              void* d_out, int out_size)
{
    (void)in_sizes; (void)n_in; (void)out_size;
    const float* x    = (const float*)d_in[0];
    const float* Wr   = (const float*)d_in[1];
    const float* gr   = (const float*)d_in[2];
    const float* br   = (const float*)d_in[3];
    const float* mr   = (const float*)d_in[4];
    const float* vr   = (const float*)d_in[5];
    const float* Wb   = (const float*)d_in[6];
    const float* gb   = (const float*)d_in[7];
    const float* bbi  = (const float*)d_in[8];
    const float* mb   = (const float*)d_in[9];
    const float* vb   = (const float*)d_in[10];
    const float* Wg1  = (const float*)d_in[11];
    const float* g1g  = (const float*)d_in[12];
    const float* g1b  = (const float*)d_in[13];
    const float* g1m  = (const float*)d_in[14];
    const float* g1v  = (const float*)d_in[15];
    const float* Wg2  = (const float*)d_in[16];
    const float* g2g  = (const float*)d_in[17];
    const float* g2b  = (const float*)d_in[18];
    const float* g2m  = (const float*)d_in[19];
    const float* g2v  = (const float*)d_in[20];
    const float* Wd   = (const float*)d_in[21];
    const float* gdg  = (const float*)d_in[22];
    const float* gdb  = (const float*)d_in[23];
    const float* gdm  = (const float*)d_in[24];
    const float* gdv  = (const float*)d_in[25];
    float* out = (float*)d_out;

    cudaFuncSetAttribute(k_dist, cudaFuncAttributeMaxDynamicSharedMemorySize,
                         DIST_SMEM_BYTES);

    k_prologue<<<dim3(32, 4), 128>>>(x, Wr, gr, br, mr, vr, Wb, gb, bbi, mb, vb);
    k_foldw<<<48, 256>>>(Wd, gdg, gdv);
    k_dist<<<dim3(32, 32, 4), 256, DIST_SMEM_BYTES>>>(x);
    k_sel<<<dim3(4096, 4), 128>>>();
    k_epilogue<<<2048, 256>>>(Wg1, g1g, g1b, g1m, g1v,
                              Wg2, g2g, g2b, g2m, g2v,
                              gdg, gdb, gdm, gdv, out);
}